// round 6
// baseline (speedup 1.0000x reference)
#include <cuda_runtime.h>
#include <cuda_fp16.h>

#define N_NODES 50000
#define N_EDGES 1600000
#define BATCH   4
#define T_STEPS 50
#define DT      0.02f
#define NTILES  4
#define TILE_N  12500
#define TILE_BYTES (TILE_N * 8)          // fp16x4 per node
#define NBINS   (N_NODES * NTILES)       // 200000 (target, src-tile) bins
#define EDGE_MAX (N_EDGES + 3 * NBINS)   // 2.2M with per-bin pad to x4
#define TN (T_STEPS * N_NODES)
#define SB 148                            // step grid
#define ST 1024                           // step block
#define SCAN_BLOCKS ((NBINS + 1023) / 1024)   // 196

// ---- scratch (static device globals; no allocation allowed) ----
__device__ int      g_deg[NBINS];
__device__ int      g_row[NBINS + 1];
__device__ int      g_cur[NBINS];
__device__ int      g_btot[256];
__device__ int      g_boff[256];
__device__ unsigned g_edges2[EDGE_MAX];      // (local_src<<16) | fp16(weight)
__device__ uint2    g_rates_h[2][N_NODES];   // fp16x4 rates, double-buffered
__device__ float    g_v4[N_NODES * 4];       // v, layout n*4+q
__device__ float    g_alpha[N_NODES];

// ---------------------------------------------------------------------------
// Setup
// ---------------------------------------------------------------------------

__global__ void init_kernel(const float* __restrict__ bias,
                            const float* __restrict__ tc) {
    int i = blockIdx.x * blockDim.x + threadIdx.x;
    if (i < NBINS) g_deg[i] = 0;
    if (i >= N_NODES) return;
    float b   = bias[i];
    float tau = fmaxf(tc[i], DT);
    g_alpha[i] = DT / tau;
    #pragma unroll
    for (int q = 0; q < 4; q++) g_v4[i * 4 + q] = b;
    __half  rh = __float2half_rn(fmaxf(b, 0.0f));
    __half2 r2 = __halves2half2(rh, rh);
    uint2 p; p.x = *(unsigned*)&r2; p.y = p.x;
    g_rates_h[0][i] = p;
}

__global__ void hist_kernel(const int* __restrict__ src,
                            const int* __restrict__ tgt) {
    int e = blockIdx.x * blockDim.x + threadIdx.x;
    if (e >= N_EDGES) return;
    int bin = tgt[e] * NTILES + src[e] / TILE_N;
    atomicAdd(&g_deg[bin], 1);
}

// ---- 3-phase exclusive scan over padded bin degrees ----
__global__ void scanA_kernel() {
    int i   = blockIdx.x * 1024 + threadIdx.x;
    int val = (i < NBINS) ? ((g_deg[i] + 3) & ~3) : 0;
    int lane = threadIdx.x & 31, wid = threadIdx.x >> 5;
    int inc = val;
    #pragma unroll
    for (int d = 1; d < 32; d <<= 1) {
        int y = __shfl_up_sync(0xffffffffu, inc, d);
        if (lane >= d) inc += y;
    }
    __shared__ int ws[32];
    if (lane == 31) ws[wid] = inc;
    __syncthreads();
    if (wid == 0) {
        int w = ws[lane];
        #pragma unroll
        for (int d = 1; d < 32; d <<= 1) {
            int y = __shfl_up_sync(0xffffffffu, w, d);
            if (lane >= d) w += y;
        }
        ws[lane] = w;
    }
    __syncthreads();
    int excl = (inc - val) + (wid > 0 ? ws[wid - 1] : 0);
    if (i < NBINS) g_row[i] = excl;               // pre-offset, fixed in scanC
    if (threadIdx.x == 1023) g_btot[blockIdx.x] = excl + val;
}

__global__ void scanB_kernel() {                  // 1 block, 256 threads
    int i = threadIdx.x;
    int val = (i < SCAN_BLOCKS) ? g_btot[i] : 0;
    int lane = i & 31, wid = i >> 5;
    int inc = val;
    #pragma unroll
    for (int d = 1; d < 32; d <<= 1) {
        int y = __shfl_up_sync(0xffffffffu, inc, d);
        if (lane >= d) inc += y;
    }
    __shared__ int ws[8];
    if (lane == 31) ws[wid] = inc;
    __syncthreads();
    if (wid == 0 && lane < 8) {
        int w = ws[lane];
        #pragma unroll
        for (int d = 1; d < 8; d <<= 1) {
            int y = __shfl_up_sync(0xffu, w, d);
            if (lane >= d) w += y;
        }
        ws[lane] = w;
    }
    __syncthreads();
    int excl = (inc - val) + (wid > 0 ? ws[wid - 1] : 0);
    if (i < 256) g_boff[i] = excl;
}

__global__ void scanC_kernel() {
    int i = blockIdx.x * 1024 + threadIdx.x;
    if (i >= NBINS) return;
    int v = g_row[i] + g_boff[blockIdx.x];
    g_row[i] = v;
    g_cur[i] = v;
    if (i == NBINS - 1) g_row[NBINS] = v + ((g_deg[i] + 3) & ~3);
}

__global__ void build_kernel(const int*   __restrict__ src,
                             const int*   __restrict__ tgt,
                             const float* __restrict__ sign,
                             const float* __restrict__ cnt,
                             const float* __restrict__ strg) {
    int e = blockIdx.x * blockDim.x + threadIdx.x;
    if (e >= N_EDGES) return;
    float w = sign[e] * fmaxf(cnt[e], 0.0f) * fmaxf(strg[e], 0.0f);
    unsigned hw = (unsigned)__half_as_ushort(__float2half_rn(w));
    int s    = src[e];
    int tile = s / TILE_N;
    int loc  = s - tile * TILE_N;
    int bin  = tgt[e] * NTILES + tile;
    int pos  = atomicAdd(&g_cur[bin], 1);
    g_edges2[pos] = ((unsigned)loc << 16) | hw;
}

__global__ void pad_kernel() {                    // zero-fill bin padding
    int b = blockIdx.x * blockDim.x + threadIdx.x;
    if (b >= NBINS) return;
    int e = g_cur[b], end = g_row[b + 1];
    for (; e < end; e++) g_edges2[e] = 0u;        // loc=0, w=+0.0h dummy
}

// ---------------------------------------------------------------------------
// Step kernel: SMEM-tiled gather. Each block stages 12.5K-node fp16x4 rate
// tiles in shared (double-buffered via cp.async) and gathers with LDS —
// off the L1tex divergent-replay path. Quad lanes split each bin's edges;
// each lane accumulates all 4 batch components, quad-reduced at the end.
// ---------------------------------------------------------------------------

__device__ __forceinline__ void cp_tile(uint2* dst, const uint2* src, int tid) {
    unsigned sd = (unsigned)__cvta_generic_to_shared(dst);
    const char* g = (const char*)src;
    for (int i = tid * 16; i < TILE_BYTES; i += ST * 16)
        asm volatile("cp.async.cg.shared.global [%0], [%1], 16;"
                     :: "r"(sd + i), "l"(g + i));
}

__device__ __forceinline__ void bin_acc(int e0, int e1, int q,
                                        const uint2* __restrict__ cur,
                                        float* acc) {
    for (int e = e0 + q; e < e1; e += 4) {
        unsigned w32 = __ldg(&g_edges2[e]);
        int   sl = w32 >> 16;
        float wt = __half2float(__ushort_as_half((unsigned short)w32));
        uint2 rh = cur[sl];
        float2 f01 = __half22float2(*(const __half2*)&rh.x);
        float2 f23 = __half22float2(*(const __half2*)&rh.y);
        acc[0] += f01.x * wt;
        acc[1] += f01.y * wt;
        acc[2] += f23.x * wt;
        acc[3] += f23.y * wt;
    }
}

__global__ __launch_bounds__(ST, 1)
void step_kernel(const float* __restrict__ x,
                 const float* __restrict__ bias,
                 float* __restrict__ out,
                 int t, int parity) {
    extern __shared__ uint2 sbuf[];               // 2 * TILE_N
    uint2* bufs[2] = { sbuf, sbuf + TILE_N };
    const int tid = threadIdx.x;
    const int nb0 = (int)(((long long)N_NODES * blockIdx.x) / SB);
    const int nb1 = (int)(((long long)N_NODES * (blockIdx.x + 1)) / SB);
    const int s1  = nb1 * 4;

    int  sA = nb0 * 4 + tid;
    int  sB = sA + ST;
    bool vB = sB < s1;
    bool wB = __any_sync(0xffffffffu, vB);

    int nA = sA >> 2, qA = sA & 3;
    int nB = vB ? (sB >> 2) : nA, qB = sB & 3;

    int rA[NTILES + 1], rB[NTILES + 1];
    #pragma unroll
    for (int k = 0; k <= NTILES; k++) rA[k] = g_row[nA * NTILES + k];
    #pragma unroll
    for (int k = 0; k <= NTILES; k++) rB[k] = vB ? g_row[nB * NTILES + k] : 0;

    int   oA = t * N_NODES + nA, xiA = qA * TN + oA;
    float xvA = __ldcs(&x[xiA]);
    int   oB = t * N_NODES + nB, xiB = qB * TN + oB;
    float xvB = vB ? __ldcs(&x[xiB]) : 0.f;

    float accA[4] = {0.f, 0.f, 0.f, 0.f};
    float accB[4] = {0.f, 0.f, 0.f, 0.f};
    const uint2* rsrc = g_rates_h[parity];

    cp_tile(bufs[0], rsrc, tid);
    asm volatile("cp.async.commit_group;");
    asm volatile("cp.async.wait_group 0;");
    __syncthreads();

    #pragma unroll
    for (int tl = 0; tl < NTILES; tl++) {
        if (tl + 1 < NTILES) {
            cp_tile(bufs[(tl + 1) & 1], rsrc + (tl + 1) * TILE_N, tid);
            asm volatile("cp.async.commit_group;");
        }
        const uint2* cur = bufs[tl & 1];
        bin_acc(rA[tl], rA[tl + 1], qA, cur, accA);
        if (wB) bin_acc(rB[tl], rB[tl + 1], qB, cur, accB);
        if (tl + 1 < NTILES) {
            asm volatile("cp.async.wait_group 0;");
            __syncthreads();
        }
    }

    // quad reduction of all 4 components (warp reconverged)
    #pragma unroll
    for (int off = 1; off <= 2; off <<= 1) {
        #pragma unroll
        for (int k = 0; k < 4; k++) {
            accA[k] += __shfl_xor_sync(0xffffffffu, accA[k], off);
            accB[k] += __shfl_xor_sync(0xffffffffu, accB[k], off);
        }
    }
    float sumA = (qA == 0) ? accA[0] : (qA == 1) ? accA[1]
               : (qA == 2) ? accA[2] : accA[3];
    float sumB = (qB == 0) ? accB[0] : (qB == 1) ? accB[1]
               : (qB == 2) ? accB[2] : accB[3];

    __half* wr = (__half*)g_rates_h[parity ^ 1];

    {   // Euler update A
        float b = bias[nA], a = g_alpha[nA];
        float v = g_v4[sA];
        v += a * (b - v + sumA + xvA);
        g_v4[sA] = v;
        float r = fmaxf(v, 0.f);
        wr[sA] = __float2half_rn(r);
        __stcs(&out[xiA], r);
    }
    if (vB) {
        float b = bias[nB], a = g_alpha[nB];
        float v = g_v4[sB];
        v += a * (b - v + sumB + xvB);
        g_v4[sB] = v;
        float r = fmaxf(v, 0.f);
        wr[sB] = __float2half_rn(r);
        __stcs(&out[xiB], r);
    }
}

// ---------------------------------------------------------------------------

extern "C" void kernel_launch(void* const* d_in, const int* in_sizes, int n_in,
                              void* d_out, int out_size) {
    const float* x    = (const float*)d_in[0];
    const float* bias = (const float*)d_in[1];
    const float* tc   = (const float*)d_in[2];
    const float* sign = (const float*)d_in[3];
    const float* cnt  = (const float*)d_in[4];
    const float* strg = (const float*)d_in[5];
    const int*   src  = (const int*)d_in[6];
    const int*   tgt  = (const int*)d_in[7];
    float*       out  = (float*)d_out;

    cudaFuncSetAttribute(step_kernel,
                         cudaFuncAttributeMaxDynamicSharedMemorySize,
                         2 * TILE_BYTES);

    int ib = (NBINS + 255) / 256;
    int eb = (N_EDGES + 255) / 256;

    init_kernel<<<ib, 256>>>(bias, tc);
    hist_kernel<<<eb, 256>>>(src, tgt);
    scanA_kernel<<<SCAN_BLOCKS, 1024>>>();
    scanB_kernel<<<1, 256>>>();
    scanC_kernel<<<SCAN_BLOCKS, 1024>>>();
    build_kernel<<<eb, 256>>>(src, tgt, sign, cnt, strg);
    pad_kernel<<<ib, 256>>>();

    for (int t = 0; t < T_STEPS; t++)
        step_kernel<<<SB, ST, 2 * TILE_BYTES>>>(x, bias, out, t, t & 1);
}

// round 7
// speedup vs baseline: 1.0289x; 1.0289x over previous
#include <cuda_runtime.h>
#include <cuda_fp16.h>

#define N_NODES 50000
#define N_EDGES 1600000
#define BATCH   4
#define T_STEPS 50
#define DT      0.02f
#define NTILES  4
#define TILE_N  12500
#define TILE_BYTES (TILE_N * 8)          // fp16x4 per node
#define NCHUNK  (TILE_BYTES / 16)        // 6250 16B chunks per tile
#define NBINS   (N_NODES * NTILES)       // 200000 (target, src-tile) bins
#define EDGE_MAX (N_EDGES + 3 * NBINS)
#define TN (T_STEPS * N_NODES)
#define SB 148
#define ST 1024
#define SCAN_BLOCKS ((NBINS + 1023) / 1024)   // 196

// ---- scratch (static device globals; no allocation allowed) ----
__device__ int      g_deg[NBINS];
__device__ int      g_row[NBINS + 1];
__device__ int      g_cur[NBINS];
__device__ int      g_btot[256];
__device__ int      g_boff[256];
__device__ unsigned g_edges2[EDGE_MAX];      // (local_src<<16) | fp16(weight)
__device__ uint2    g_rates_h[2][N_NODES];   // fp16x4 rates, double-buffered
__device__ float    g_v4[N_NODES * 4];
__device__ float    g_alpha[N_NODES];

// ---------------------------------------------------------------------------
// Setup
// ---------------------------------------------------------------------------

__global__ void init_kernel(const float* __restrict__ bias,
                            const float* __restrict__ tc) {
    int i = blockIdx.x * blockDim.x + threadIdx.x;
    if (i < NBINS) g_deg[i] = 0;
    if (i >= N_NODES) return;
    float b   = bias[i];
    float tau = fmaxf(tc[i], DT);
    g_alpha[i] = DT / tau;
    #pragma unroll
    for (int q = 0; q < 4; q++) g_v4[i * 4 + q] = b;
    __half  rh = __float2half_rn(fmaxf(b, 0.0f));
    __half2 r2 = __halves2half2(rh, rh);
    uint2 p; p.x = *(unsigned*)&r2; p.y = p.x;
    g_rates_h[0][i] = p;
}

__global__ void hist_kernel(const int* __restrict__ src,
                            const int* __restrict__ tgt) {
    int e = blockIdx.x * blockDim.x + threadIdx.x;
    if (e >= N_EDGES) return;
    int bin = tgt[e] * NTILES + src[e] / TILE_N;
    atomicAdd(&g_deg[bin], 1);
}

// ---- 3-phase exclusive scan over padded bin degrees ----
__global__ void scanA_kernel() {
    int i   = blockIdx.x * 1024 + threadIdx.x;
    int val = (i < NBINS) ? ((g_deg[i] + 3) & ~3) : 0;
    int lane = threadIdx.x & 31, wid = threadIdx.x >> 5;
    int inc = val;
    #pragma unroll
    for (int d = 1; d < 32; d <<= 1) {
        int y = __shfl_up_sync(0xffffffffu, inc, d);
        if (lane >= d) inc += y;
    }
    __shared__ int ws[32];
    if (lane == 31) ws[wid] = inc;
    __syncthreads();
    if (wid == 0) {
        int w = ws[lane];
        #pragma unroll
        for (int d = 1; d < 32; d <<= 1) {
            int y = __shfl_up_sync(0xffffffffu, w, d);
            if (lane >= d) w += y;
        }
        ws[lane] = w;
    }
    __syncthreads();
    int excl = (inc - val) + (wid > 0 ? ws[wid - 1] : 0);
    if (i < NBINS) g_row[i] = excl;
    if (threadIdx.x == 1023) g_btot[blockIdx.x] = excl + val;
}

__global__ void scanB_kernel() {
    int i = threadIdx.x;
    int val = (i < SCAN_BLOCKS) ? g_btot[i] : 0;
    int lane = i & 31, wid = i >> 5;
    int inc = val;
    #pragma unroll
    for (int d = 1; d < 32; d <<= 1) {
        int y = __shfl_up_sync(0xffffffffu, inc, d);
        if (lane >= d) inc += y;
    }
    __shared__ int ws[8];
    if (lane == 31) ws[wid] = inc;
    __syncthreads();
    if (wid == 0 && lane < 8) {
        int w = ws[lane];
        #pragma unroll
        for (int d = 1; d < 8; d <<= 1) {
            int y = __shfl_up_sync(0xffu, w, d);
            if (lane >= d) w += y;
        }
        ws[lane] = w;
    }
    __syncthreads();
    int excl = (inc - val) + (wid > 0 ? ws[wid - 1] : 0);
    if (i < 256) g_boff[i] = excl;
}

__global__ void scanC_kernel() {
    int i = blockIdx.x * 1024 + threadIdx.x;
    if (i >= NBINS) return;
    int v = g_row[i] + g_boff[blockIdx.x];
    g_row[i] = v;
    g_cur[i] = v;
    if (i == NBINS - 1) g_row[NBINS] = v + ((g_deg[i] + 3) & ~3);
}

__global__ void build_kernel(const int*   __restrict__ src,
                             const int*   __restrict__ tgt,
                             const float* __restrict__ sign,
                             const float* __restrict__ cnt,
                             const float* __restrict__ strg) {
    int e = blockIdx.x * blockDim.x + threadIdx.x;
    if (e >= N_EDGES) return;
    float w = sign[e] * fmaxf(cnt[e], 0.0f) * fmaxf(strg[e], 0.0f);
    unsigned hw = (unsigned)__half_as_ushort(__float2half_rn(w));
    int s    = src[e];
    int tile = s / TILE_N;
    int loc  = s - tile * TILE_N;
    int bin  = tgt[e] * NTILES + tile;
    int pos  = atomicAdd(&g_cur[bin], 1);
    g_edges2[pos] = ((unsigned)loc << 16) | hw;
}

__global__ void pad_kernel() {
    int b = blockIdx.x * blockDim.x + threadIdx.x;
    if (b >= NBINS) return;
    int e = g_cur[b], end = g_row[b + 1];
    for (; e < end; e++) g_edges2[e] = 0u;        // loc=0, w=+0.0h dummy
}

// ---------------------------------------------------------------------------
// Step kernel: SMEM-tiled gather with tile ROTATION (block b starts at tile
// b&3) and staggered chunk order inside each tile load — spreads L2 traffic
// so the 148-block broadcast doesn't camp on a few LTS slices. Edge words
// loaded 4-at-a-time per lane (LDG.128). Quad lanes split each bin; each
// lane accumulates all 4 batch components; quad shfl reduce at the end.
// ---------------------------------------------------------------------------

__device__ __forceinline__ void cp_tile(uint2* dst, const uint2* src,
                                        int tid, int rot) {
    unsigned sd = (unsigned)__cvta_generic_to_shared(dst);
    const char* g = (const char*)src;
    for (int k = tid; k < NCHUNK; k += ST) {
        int c = k + rot; if (c >= NCHUNK) c -= NCHUNK;
        asm volatile("cp.async.cg.shared.global [%0], [%1], 16;"
                     :: "r"(sd + c * 16), "l"(g + c * 16));
    }
}

__device__ __forceinline__ void word_acc(unsigned w,
                                         const uint2* __restrict__ cur,
                                         float* acc) {
    int   sl = w >> 16;
    float wt = __half2float(__ushort_as_half((unsigned short)w));
    uint2 rh = cur[sl];
    float2 f01 = __half22float2(*(const __half2*)&rh.x);
    float2 f23 = __half22float2(*(const __half2*)&rh.y);
    acc[0] += f01.x * wt;
    acc[1] += f01.y * wt;
    acc[2] += f23.x * wt;
    acc[3] += f23.y * wt;
}

__device__ __forceinline__ void bin_acc(int e0, int e1, int q,
                                        const uint2* __restrict__ cur,
                                        float* acc) {
    // lane q takes 4-word groups: [e0+4q, +16, ...] — LDG.128, 4 edges/load
    for (int e = e0 + 4 * q; e < e1; e += 16) {
        uint4 w4 = __ldg((const uint4*)&g_edges2[e]);
        word_acc(w4.x, cur, acc);
        word_acc(w4.y, cur, acc);
        word_acc(w4.z, cur, acc);
        word_acc(w4.w, cur, acc);
    }
}

__global__ __launch_bounds__(ST, 1)
void step_kernel(const float* __restrict__ x,
                 const float* __restrict__ bias,
                 float* __restrict__ out,
                 int t, int parity) {
    extern __shared__ uint2 sbuf[];
    uint2* bufs[2] = { sbuf, sbuf + TILE_N };
    const int tid = threadIdx.x;
    const int blk = blockIdx.x;
    const int nb0 = (int)(((long long)N_NODES * blk) / SB);
    const int nb1 = (int)(((long long)N_NODES * (blk + 1)) / SB);
    const int s1  = nb1 * 4;
    const int rot = (blk * 1567) % NCHUNK;   // per-block stagger
    const int p0  = blk & 3;                 // starting tile (rotation)

    int  sA = nb0 * 4 + tid;
    int  sB = sA + ST;
    bool vB = sB < s1;
    bool wB = __any_sync(0xffffffffu, vB);

    int nA = sA >> 2, qA = sA & 3;
    int nB = vB ? (sB >> 2) : nA, qB = sB & 3;

    int rA[NTILES + 1], rB[NTILES + 1];
    #pragma unroll
    for (int k = 0; k <= NTILES; k++) rA[k] = g_row[nA * NTILES + k];
    #pragma unroll
    for (int k = 0; k <= NTILES; k++) rB[k] = vB ? g_row[nB * NTILES + k] : 0;

    int   xiA = qA * TN + t * N_NODES + nA;
    float xvA = __ldcs(&x[xiA]);
    int   xiB = qB * TN + t * N_NODES + nB;
    float xvB = vB ? __ldcs(&x[xiB]) : 0.f;

    float accA[4] = {0.f, 0.f, 0.f, 0.f};
    float accB[4] = {0.f, 0.f, 0.f, 0.f};
    const uint2* rsrc = g_rates_h[parity];

    cp_tile(bufs[0], rsrc + p0 * TILE_N, tid, rot);
    asm volatile("cp.async.commit_group;");
    asm volatile("cp.async.wait_group 0;");
    __syncthreads();

    #pragma unroll
    for (int i = 0; i < NTILES; i++) {
        int phys = (p0 + i) & 3;
        if (i + 1 < NTILES) {
            cp_tile(bufs[(i + 1) & 1], rsrc + ((p0 + i + 1) & 3) * TILE_N,
                    tid, rot);
            asm volatile("cp.async.commit_group;");
        }
        const uint2* cur = bufs[i & 1];
        bin_acc(rA[phys], rA[phys + 1], qA, cur, accA);
        if (wB) bin_acc(rB[phys], rB[phys + 1], qB, cur, accB);
        if (i + 1 < NTILES) {
            asm volatile("cp.async.wait_group 0;");
            __syncthreads();
        }
    }

    #pragma unroll
    for (int off = 1; off <= 2; off <<= 1) {
        #pragma unroll
        for (int k = 0; k < 4; k++) {
            accA[k] += __shfl_xor_sync(0xffffffffu, accA[k], off);
            accB[k] += __shfl_xor_sync(0xffffffffu, accB[k], off);
        }
    }
    float sumA = (qA == 0) ? accA[0] : (qA == 1) ? accA[1]
               : (qA == 2) ? accA[2] : accA[3];
    float sumB = (qB == 0) ? accB[0] : (qB == 1) ? accB[1]
               : (qB == 2) ? accB[2] : accB[3];

    __half* wr = (__half*)g_rates_h[parity ^ 1];

    {
        float b = bias[nA], a = g_alpha[nA];
        float v = g_v4[sA];
        v += a * (b - v + sumA + xvA);
        g_v4[sA] = v;
        float r = fmaxf(v, 0.f);
        wr[sA] = __float2half_rn(r);
        __stcs(&out[xiA], r);
    }
    if (vB) {
        float b = bias[nB], a = g_alpha[nB];
        float v = g_v4[sB];
        v += a * (b - v + sumB + xvB);
        g_v4[sB] = v;
        float r = fmaxf(v, 0.f);
        wr[sB] = __float2half_rn(r);
        __stcs(&out[xiB], r);
    }
}

// ---------------------------------------------------------------------------

extern "C" void kernel_launch(void* const* d_in, const int* in_sizes, int n_in,
                              void* d_out, int out_size) {
    const float* x    = (const float*)d_in[0];
    const float* bias = (const float*)d_in[1];
    const float* tc   = (const float*)d_in[2];
    const float* sign = (const float*)d_in[3];
    const float* cnt  = (const float*)d_in[4];
    const float* strg = (const float*)d_in[5];
    const int*   src  = (const int*)d_in[6];
    const int*   tgt  = (const int*)d_in[7];
    float*       out  = (float*)d_out;

    cudaFuncSetAttribute(step_kernel,
                         cudaFuncAttributeMaxDynamicSharedMemorySize,
                         2 * TILE_BYTES);

    int ib = (NBINS + 255) / 256;
    int eb = (N_EDGES + 255) / 256;

    init_kernel<<<ib, 256>>>(bias, tc);
    hist_kernel<<<eb, 256>>>(src, tgt);
    scanA_kernel<<<SCAN_BLOCKS, 1024>>>();
    scanB_kernel<<<1, 256>>>();
    scanC_kernel<<<SCAN_BLOCKS, 1024>>>();
    build_kernel<<<eb, 256>>>(src, tgt, sign, cnt, strg);
    pad_kernel<<<ib, 256>>>();

    for (int t = 0; t < T_STEPS; t++)
        step_kernel<<<SB, ST, 2 * TILE_BYTES>>>(x, bias, out, t, t & 1);
}